// round 7
// baseline (speedup 1.0000x reference)
#include <cuda_runtime.h>
#include <cuda_fp16.h>
#include <math.h>
#include <stdint.h>

#define B_    32
#define CIN   3
#define HIN   224
#define WIN   224
#define CO    192
#define OH    112
#define OW    112
#define PH    56
#define PW    56
#define NPC   (B_*OH*OW)   // 401408

// padded y layout: per (b,c) plane = 113 rows x 128 halves.
// row 0 = NaN halo; y row r stored at row r+1; y col c stored at col c+4.
// cols 0..3 and 116..127 are NaN halo.
#define PP     128
#define PROWS  113

// -------- device scratch ----------------------------------------------------
__device__ __half g_yh[(size_t)B_*CO*PROWS*PP];   // ~178 MB padded conv output
__device__ __half g_wh[CO*32];                    // fp16 weights, taps 27..31 = 0
__device__ float g_sum[CO];                       // zeroed at load; finalize re-zeroes
__device__ float g_sq[CO];
__device__ float g_scale[CO];
__device__ float g_shift[CO];

// ---------------------------------------------------------------------------
__global__ void wprep_kernel(const float* __restrict__ conv_w) {
    int i = blockIdx.x*256 + threadIdx.x;
    if (i >= CO*32) return;
    int co = i >> 5, k = i & 31;
    float v = (k < 27) ? conv_w[co*27 + k] : 0.f;
    g_wh[i] = __float2half(v);
}

// ---------------------------------------------------------------------------
__device__ __forceinline__ void mma16816(float& d0, float& d1, float& d2, float& d3,
                                         uint32_t a0, uint32_t a1, uint32_t a2, uint32_t a3,
                                         uint32_t b0, uint32_t b1) {
    asm volatile(
        "mma.sync.aligned.m16n8k16.row.col.f32.f16.f16.f32 "
        "{%0,%1,%2,%3},{%4,%5,%6,%7},{%8,%9},{%0,%1,%2,%3};"
        : "+f"(d0), "+f"(d1), "+f"(d2), "+f"(d3)
        : "r"(a0), "r"(a1), "r"(a2), "r"(a3), "r"(b0), "r"(b1));
}

// ---------------------------------------------------------------------------
// Implicit-GEMM conv, 4 output rows per block (A build + staging amortized).
// 448 thr = 14 warps. Warp w: mh=w&1 -> 96 channels, ng=w>>1 -> 16 cols.
#define CONV_THREADS 448
#define RPB     4
#define XROWS   9                       // 2*RPB+1 input rows
#define XPITCH  232
#define APITCH  40
#define BPITCH  40
#define A_OFF   0                       // 192*40 = 7680 halves
#define X_OFF   (CO*APITCH)             // 3*9*232 = 6264 halves
#define B_OFF   (X_OFF + CIN*XROWS*XPITCH)
#define H_TOT   (B_OFF + OW*BPITCH)     // 7680+6264+4480 = 18424 halves
#define CONV_SMEM (H_TOT*2 + 576*4)     // 36848 + 2304 = 39152 B

__global__ __launch_bounds__(CONV_THREADS, 2)
void conv_mma_kernel(const float* __restrict__ x,
                     const float* __restrict__ conv_b) {
    extern __shared__ __half sm[];
    __half* A_s = sm + A_OFF;
    __half* sX  = sm + X_OFF;
    __half* B_s = sm + B_OFF;
    float*  sBias = (float*)(sm + H_TOT);
    float*  sSum  = sBias + 192;
    float*  sSq   = sBias + 384;

    const int tid  = threadIdx.x;
    const int lane = tid & 31;
    const int w    = tid >> 5;
    const int rt   = blockIdx.x;    // 4-row tile, 0..27
    const int b    = blockIdx.y;

    if (tid < 192) {
        sBias[tid] = conv_b[tid];
        sSum[tid] = 0.f;
        sSq [tid] = 0.f;
    }

    // ---- A: copy prebuilt fp16 weights (uint2 halves at a time) ----
    {
        const uint32_t* src = (const uint32_t*)g_wh;
        uint32_t* dst = (uint32_t*)A_s;          // pitch 20 uints
        for (int i = tid; i < CO*16; i += CONV_THREADS) {
            int co = i >> 4, ku = i & 15;
            dst[co*20 + ku] = src[i];
        }
    }

    // ---- stage 9 input rows x 3 ci as fp16, cols -1..224 ----
    {
        const int gr_base = 8*rt - 1;
        for (int i = tid; i < CIN*XROWS*226; i += CONV_THREADS) {
            int r9 = i / 226;
            int c  = i - r9*226;
            int ci = r9 / XROWS;
            int r  = r9 - ci*XROWS;
            int gr = gr_base + r;
            int gc = c - 1;
            float v = 0.f;
            if (gr >= 0 && gr < HIN && gc >= 0 && gc < WIN)
                v = x[((size_t)(b*CIN + ci)*HIN + gr)*WIN + gc];
            sX[(ci*XROWS + r)*XPITCH + c] = __float2half(v);
        }
    }

    // ---- NaN halo writes (pure STG, pool reads these as padding) ----
    {
        const __half2 NH2 = __halves2half2(__ushort_as_half((unsigned short)0x7e00),
                                           __ushort_as_half((unsigned short)0x7e00));
        // left cols 0..3, right cols 116..127 for this block's 4 rows, all ch
        for (int i = tid; i < 192*RPB*8; i += CONV_THREADS) {
            int j   = i & 7;
            int row = (i >> 3) & 3;
            int ch  = i >> 5;
            int col = (j < 2) ? 2*j : 116 + 2*(j - 2);
            *(__half2*)(g_yh + ((size_t)(b*CO + ch)*PROWS + 4*rt + row + 1)*PP + col) = NH2;
        }
        if (rt == 0) {   // top halo row 0, all channels
            for (int i = tid; i < 192*64; i += CONV_THREADS) {
                int ch = i >> 6;
                int j  = i & 63;
                *(__half2*)(g_yh + ((size_t)(b*CO + ch)*PROWS)*PP + 2*j) = NH2;
            }
        }
    }
    __syncthreads();

    const int mh = w & 1;
    const int ng = w >> 1;
    const int qr = lane >> 2;
    const int qc = lane & 3;

    #pragma unroll 1
    for (int oyl = 0; oyl < RPB; ++oyl) {
        // ---- build B [112 n][40 k]: warp = one n per pass, lane = k ----
        {
            int ci = lane / 9;
            int rr = lane - ci*9;
            int ky = rr / 3;
            int kx = rr - ky*3;
            const __half* xs = &sX[(ci*XROWS + 2*oyl + ky)*XPITCH + kx];
            #pragma unroll
            for (int j = 0; j < 8; ++j) {
                int n = w + 14*j;
                __half v = __float2half(0.f);
                if (lane < 27) v = xs[2*n];
                B_s[n*BPITCH + lane] = v;
            }
        }
        __syncthreads();

        // ---- MMA ----
        float acc[6][2][4];
        #pragma unroll
        for (int mi = 0; mi < 6; ++mi)
            #pragma unroll
            for (int ni = 0; ni < 2; ++ni)
                #pragma unroll
                for (int j = 0; j < 4; ++j) acc[mi][ni][j] = 0.f;

        #pragma unroll
        for (int ks = 0; ks < 2; ++ks) {
            const int kb = ks*16 + 2*qc;
            uint32_t bf[2][2];
            #pragma unroll
            for (int ni = 0; ni < 2; ++ni) {
                const __half* bp = &B_s[(ng*16 + ni*8 + qr)*BPITCH + kb];
                bf[ni][0] = *(const uint32_t*)(bp);
                bf[ni][1] = *(const uint32_t*)(bp + 8);
            }
            #pragma unroll
            for (int mi = 0; mi < 6; ++mi) {
                const int R = (mh*6 + mi)*16 + qr;
                const __half* ap = &A_s[R*APITCH + kb];
                uint32_t a0 = *(const uint32_t*)(ap);
                uint32_t a1 = *(const uint32_t*)(ap + 8*APITCH);
                uint32_t a2 = *(const uint32_t*)(ap + 8);
                uint32_t a3 = *(const uint32_t*)(ap + 8*APITCH + 8);
                #pragma unroll
                for (int ni = 0; ni < 2; ++ni)
                    mma16816(acc[mi][ni][0], acc[mi][ni][1], acc[mi][ni][2], acc[mi][ni][3],
                             a0, a1, a2, a3, bf[ni][0], bf[ni][1]);
            }
        }

        // ---- epilogue: bias, padded fp16 store, stats ----
        const int OY = 4*rt + oyl;
        #pragma unroll
        for (int mi = 0; mi < 6; ++mi) {
            const int R0 = (mh*6 + mi)*16 + qr;
            const int R8 = R0 + 8;
            const float bias0 = sBias[R0];
            const float bias8 = sBias[R8];
            float s0 = 0.f, q0 = 0.f, s8 = 0.f, q8 = 0.f;
            #pragma unroll
            for (int ni = 0; ni < 2; ++ni) {
                const int C = ng*16 + ni*8 + 2*qc;
                float v0 = acc[mi][ni][0] + bias0;
                float v1 = acc[mi][ni][1] + bias0;
                float v2 = acc[mi][ni][2] + bias8;
                float v3 = acc[mi][ni][3] + bias8;
                __half2* d0 = (__half2*)(g_yh + ((size_t)(b*CO + R0)*PROWS + OY + 1)*PP + 4 + C);
                __half2* d8 = (__half2*)(g_yh + ((size_t)(b*CO + R8)*PROWS + OY + 1)*PP + 4 + C);
                *d0 = __floats2half2_rn(v0, v1);
                *d8 = __floats2half2_rn(v2, v3);
                s0 += v0 + v1;  q0 += v0*v0 + v1*v1;
                s8 += v2 + v3;  q8 += v2*v2 + v3*v3;
            }
            #pragma unroll
            for (int o = 1; o <= 2; o <<= 1) {
                s0 += __shfl_xor_sync(0xffffffffu, s0, o);
                q0 += __shfl_xor_sync(0xffffffffu, q0, o);
                s8 += __shfl_xor_sync(0xffffffffu, s8, o);
                q8 += __shfl_xor_sync(0xffffffffu, q8, o);
            }
            if (qc == 0) {
                atomicAdd(&sSum[R0], s0);
                atomicAdd(&sSq [R0], q0);
                atomicAdd(&sSum[R8], s8);
                atomicAdd(&sSq [R8], q8);
            }
        }
        __syncthreads();
    }

    if (tid < 192) {
        atomicAdd(&g_sum[tid], sSum[tid]);
        atomicAdd(&g_sq [tid], sSq [tid]);
    }
}

// ---------------------------------------------------------------------------
__global__ void finalize_stats_kernel(const float* __restrict__ gamma,
                                      const float* __restrict__ beta) {
    int c = threadIdx.x;
    if (c >= CO) return;
    float invN  = 1.0f / (float)NPC;
    float mean  = g_sum[c] * invN;
    float var   = g_sq[c] * invN - mean*mean;
    float inv   = rsqrtf(var + 1e-5f);
    float scale = gamma[c] * inv;
    g_scale[c]  = scale;
    g_shift[c]  = beta[c] - mean*scale;
    g_sum[c] = 0.f;   // re-zero for next graph replay
    g_sq [c] = 0.f;
}

// ---------------------------------------------------------------------------
// BN + GELU + MaxPool via GELU unimodality:
//   max_w gelu(affine(y)) = max(gelu(affine(min_w y)), gelu(affine(max_w y)))
// y is already NaN-padded in gmem -> straight float4 copy, no halo logic.
#define POOL_THREADS 224
#define POOL_SMEM (PROWS*PP*2)     // 28928 B

__global__ __launch_bounds__(POOL_THREADS)
void bn_gelu_pool_kernel(float* __restrict__ out) {
    extern __shared__ __half sH[];
    const int c = blockIdx.x;
    const int b = blockIdx.y;
    const int tid = threadIdx.x;

    // phase 1: copy padded plane (113 x 128 halves = 1808 float4)
    const float4* src = (const float4*)(g_yh + ((size_t)(b*CO + c)*PROWS)*PP);
    float4* d4 = (float4*)sH;
    for (int i = tid; i < PROWS*PP/8; i += POOL_THREADS) d4[i] = src[i];
    __syncthreads();

    const float scale = g_scale[c];
    const float shift = g_shift[c];

    const int g  = tid % 14;
    const int ty = tid / 14;
    float* op = &out[(size_t)(b*CO + c)*(PH*PW)];
    for (int py = ty; py < PH; py += 16) {
        const __half2* q0 = (const __half2*)&sH[(2*py)*PP + 8*g + 2];
        const __half2* q1 = (const __half2*)((const __half*)q0 + PP);
        const __half2* q2 = (const __half2*)((const __half*)q1 + PP);
        __half2 vmin[5], vmax[5];
        #pragma unroll
        for (int j = 0; j < 5; ++j) {
            __half2 a = q0[j], bb = q1[j], cc = q2[j];
            vmax[j] = __hmax2(__hmax2(a, bb), cc);
            vmin[j] = __hmin2(__hmin2(a, bb), cc);
        }
        const __half* Hm = (const __half*)vmin;
        const __half* HM = (const __half*)vmax;
        float4 o;
        float* ov = (float*)&o;
        #pragma unroll
        for (int j = 0; j < 4; ++j) {
            __half wm = __hmin(Hm[2*j+1], __hmin(Hm[2*j+2], Hm[2*j+3]));
            __half wM = __hmax(HM[2*j+1], __hmax(HM[2*j+2], HM[2*j+3]));
            float a1 = fmaf(__half2float(wm), scale, shift);
            float a2 = fmaf(__half2float(wM), scale, shift);
            float g1 = 0.5f*a1*(1.0f + erff(a1*0.70710678118654752f));
            float g2 = 0.5f*a2*(1.0f + erff(a2*0.70710678118654752f));
            ov[j] = fmaxf(g1, g2);
        }
        *(float4*)&op[py*PW + 4*g] = o;
    }
}

// ---------------------------------------------------------------------------
extern "C" void kernel_launch(void* const* d_in, const int* in_sizes, int n_in,
                              void* d_out, int out_size) {
    const float* x      = (const float*)d_in[0];
    const float* conv_w = (const float*)d_in[1];
    const float* conv_b = (const float*)d_in[2];
    const float* gamma  = (const float*)d_in[3];
    const float* beta   = (const float*)d_in[4];
    float* out = (float*)d_out;

    cudaFuncSetAttribute(conv_mma_kernel,
                         cudaFuncAttributeMaxDynamicSharedMemorySize, CONV_SMEM);
    cudaFuncSetAttribute(bn_gelu_pool_kernel,
                         cudaFuncAttributeMaxDynamicSharedMemorySize, POOL_SMEM);

    wprep_kernel<<<(CO*32 + 255)/256, 256>>>(conv_w);
    conv_mma_kernel<<<dim3(28, B_), CONV_THREADS, CONV_SMEM>>>(x, conv_b);
    finalize_stats_kernel<<<1, CO>>>(gamma, beta);
    bn_gelu_pool_kernel<<<dim3(CO, B_), POOL_THREADS, POOL_SMEM>>>(out);
}

// round 8
// speedup vs baseline: 1.3029x; 1.3029x over previous
#include <cuda_runtime.h>
#include <cuda_fp16.h>
#include <math.h>
#include <stdint.h>

#define B_    32
#define CIN   3
#define HIN   224
#define WIN   224
#define CO    192
#define OH    112
#define OW    112
#define PH    56
#define PW    56
#define NPC   (B_*OH*OW)   // 401408

// padded y layout: per (b,c) plane = 113 rows x 128 halves.
// row 0 = NaN halo; y row r at row r+1; y col c at col c+4.
// cols 0..3 and 116..127 are NaN halo.
#define PP     128
#define PROWS  113

// -------- device scratch ----------------------------------------------------
__device__ __half g_yh[(size_t)B_*CO*PROWS*PP];   // ~178 MB padded conv output
__device__ __half g_wh[CO*32];                    // fp16 weights, taps 27..31 = 0
__device__ float g_sum[CO];                       // zeroed at load; finalize re-zeroes
__device__ float g_sq[CO];
__device__ float g_scale[CO];
__device__ float g_shift[CO];

// ---------------------------------------------------------------------------
__global__ void wprep_kernel(const float* __restrict__ conv_w) {
    int i = blockIdx.x*256 + threadIdx.x;
    if (i >= CO*32) return;
    int co = i >> 5, k = i & 31;
    float v = (k < 27) ? conv_w[co*27 + k] : 0.f;
    g_wh[i] = __float2half(v);
}

// ---------------------------------------------------------------------------
__device__ __forceinline__ void mma16816(float& d0, float& d1, float& d2, float& d3,
                                         uint32_t a0, uint32_t a1, uint32_t a2, uint32_t a3,
                                         uint32_t b0, uint32_t b1) {
    asm volatile(
        "mma.sync.aligned.m16n8k16.row.col.f32.f16.f16.f32 "
        "{%0,%1,%2,%3},{%4,%5,%6,%7},{%8,%9},{%0,%1,%2,%3};"
        : "+f"(d0), "+f"(d1), "+f"(d2), "+f"(d3)
        : "r"(a0), "r"(a1), "r"(a2), "r"(a3), "r"(b0), "r"(b1));
}

// ---------------------------------------------------------------------------
// Implicit-GEMM conv, 4 output rows per block.
// 448 thr = 14 warps. Warp w: mh=w&1 -> 96 channels, ng=w>>1 -> 16 cols.
// Epilogue: STS staging (conflict-free) -> coalesced STG.128 copy.
// Stats: race-free smem slots (ch x ng), one global atomic/ch at block end.
#define CONV_THREADS 448
#define RPB     4
#define XROWS   9
#define XPITCH  232
#define APITCH  40
#define BPITCH  40
#define SYP     136                          // staging pitch (halves)
#define A_OFF   0                            // 192*40  = 7680
#define X_OFF   (CO*APITCH)                  // 3*9*232 = 6264
#define B_OFF   (X_OFF + CIN*XROWS*XPITCH)   // 112*40  = 4480
#define Y_OFF   (B_OFF + OW*BPITCH)          // 192*136 = 26112
#define H_TOT   (Y_OFF + CO*SYP)             // 44536 halves
#define NF      (192 + 2*CO*9)               // bias + sum/sq slots = 3648 floats
#define CONV_SMEM (H_TOT*2 + NF*4)           // 89072 + 14592 = 103664 B

__global__ __launch_bounds__(CONV_THREADS, 2)
void conv_mma_kernel(const float* __restrict__ x,
                     const float* __restrict__ conv_b) {
    extern __shared__ __half sm[];
    __half* A_s = sm + A_OFF;
    __half* sX  = sm + X_OFF;
    __half* B_s = sm + B_OFF;
    __half* sY  = sm + Y_OFF;
    float*  sBias = (float*)(sm + H_TOT);
    float*  sSumP = sBias + 192;         // [192][9]
    float*  sSqP  = sSumP + CO*9;        // [192][9]

    const int tid  = threadIdx.x;
    const int lane = tid & 31;
    const int w    = tid >> 5;
    const int rt   = blockIdx.x;    // 4-row tile, 0..27
    const int b    = blockIdx.y;

    if (tid < 192) sBias[tid] = conv_b[tid];
    for (int i = tid; i < CO*9; i += CONV_THREADS) { sSumP[i] = 0.f; sSqP[i] = 0.f; }

    // ---- A: copy prebuilt fp16 weights ----
    {
        const uint32_t* src = (const uint32_t*)g_wh;
        uint32_t* dst = (uint32_t*)A_s;          // pitch 20 uints
        for (int i = tid; i < CO*16; i += CONV_THREADS) {
            int co = i >> 4, ku = i & 15;
            dst[co*20 + ku] = src[i];
        }
    }

    // ---- stage 9 input rows x 3 ci as fp16, cols -1..224 ----
    {
        const int gr_base = 8*rt - 1;
        for (int i = tid; i < CIN*XROWS*226; i += CONV_THREADS) {
            int r9 = i / 226;
            int c  = i - r9*226;
            int ci = r9 / XROWS;
            int r  = r9 - ci*XROWS;
            int gr = gr_base + r;
            int gc = c - 1;
            float v = 0.f;
            if (gr >= 0 && gr < HIN && gc >= 0 && gc < WIN)
                v = x[((size_t)(b*CIN + ci)*HIN + gr)*WIN + gc];
            sX[(ci*XROWS + r)*XPITCH + c] = __float2half(v);
        }
    }

    // ---- staging NaN halo cols (once): cols 0..3 and 116..127 ----
    {
        const __half2 NH2 = __halves2half2(__ushort_as_half((unsigned short)0x7e00),
                                           __ushort_as_half((unsigned short)0x7e00));
        for (int i = tid; i < CO*8; i += CONV_THREADS) {
            int ch = i >> 3, j = i & 7;
            int col = (j < 2) ? 2*j : 116 + 2*(j - 2);
            *(__half2*)&sY[ch*SYP + col] = NH2;
        }
    }

    // ---- top halo row 0 in gmem (rt==0 blocks only), coalesced uint4 ----
    if (rt == 0) {
        uint4 nv;
        nv.x = nv.y = nv.z = nv.w = 0x7e007e00u;
        for (int i = tid; i < CO*16; i += CONV_THREADS) {
            int ch = i >> 4, cu = i & 15;
            *(uint4*)(g_yh + ((size_t)(b*CO + ch)*PROWS)*PP + cu*8) = nv;
        }
    }
    __syncthreads();

    const int mh = w & 1;
    const int ng = w >> 1;
    const int qr = lane >> 2;
    const int qc = lane & 3;

    #pragma unroll 1
    for (int oyl = 0; oyl < RPB; ++oyl) {
        // ---- build B [112 n][40 k]: lane = tap, warp covers 8 n values ----
        {
            int ci = lane / 9;
            int rr = lane - ci*9;
            int ky = rr / 3;
            int kx = rr - ky*3;
            const __half* xs = &sX[(ci*XROWS + 2*oyl + ky)*XPITCH + kx];
            #pragma unroll
            for (int j = 0; j < 8; ++j) {
                int n = w + 14*j;
                __half v = __float2half(0.f);
                if (lane < 27) v = xs[2*n];
                B_s[n*BPITCH + lane] = v;
            }
        }
        __syncthreads();

        // ---- MMA ----
        float acc[6][2][4];
        #pragma unroll
        for (int mi = 0; mi < 6; ++mi)
            #pragma unroll
            for (int ni = 0; ni < 2; ++ni)
                #pragma unroll
                for (int j = 0; j < 4; ++j) acc[mi][ni][j] = 0.f;

        #pragma unroll
        for (int ks = 0; ks < 2; ++ks) {
            const int kb = ks*16 + 2*qc;
            uint32_t bf[2][2];
            #pragma unroll
            for (int ni = 0; ni < 2; ++ni) {
                const __half* bp = &B_s[(ng*16 + ni*8 + qr)*BPITCH + kb];
                bf[ni][0] = *(const uint32_t*)(bp);
                bf[ni][1] = *(const uint32_t*)(bp + 8);
            }
            #pragma unroll
            for (int mi = 0; mi < 6; ++mi) {
                const int R = (mh*6 + mi)*16 + qr;
                const __half* ap = &A_s[R*APITCH + kb];
                uint32_t a0 = *(const uint32_t*)(ap);
                uint32_t a1 = *(const uint32_t*)(ap + 8*APITCH);
                uint32_t a2 = *(const uint32_t*)(ap + 8);
                uint32_t a3 = *(const uint32_t*)(ap + 8*APITCH + 8);
                #pragma unroll
                for (int ni = 0; ni < 2; ++ni)
                    mma16816(acc[mi][ni][0], acc[mi][ni][1], acc[mi][ni][2], acc[mi][ni][3],
                             a0, a1, a2, a3, bf[ni][0], bf[ni][1]);
            }
        }

        // ---- bias, stats (smem slots, no atomics), staging STS ----
        #pragma unroll
        for (int mi = 0; mi < 6; ++mi) {
            const int R0 = (mh*6 + mi)*16 + qr;
            const int R8 = R0 + 8;
            const float bias0 = sBias[R0];
            const float bias8 = sBias[R8];
            float s0 = 0.f, q0 = 0.f, s8 = 0.f, q8 = 0.f;
            #pragma unroll
            for (int ni = 0; ni < 2; ++ni) {
                const int C = ng*16 + ni*8 + 2*qc;
                float v0 = acc[mi][ni][0] + bias0;
                float v1 = acc[mi][ni][1] + bias0;
                float v2 = acc[mi][ni][2] + bias8;
                float v3 = acc[mi][ni][3] + bias8;
                *(__half2*)&sY[R0*SYP + 4 + C] = __floats2half2_rn(v0, v1);
                *(__half2*)&sY[R8*SYP + 4 + C] = __floats2half2_rn(v2, v3);
                s0 += v0 + v1;  q0 += v0*v0 + v1*v1;
                s8 += v2 + v3;  q8 += v2*v2 + v3*v3;
            }
            #pragma unroll
            for (int o = 1; o <= 2; o <<= 1) {
                s0 += __shfl_xor_sync(0xffffffffu, s0, o);
                q0 += __shfl_xor_sync(0xffffffffu, q0, o);
                s8 += __shfl_xor_sync(0xffffffffu, s8, o);
                q8 += __shfl_xor_sync(0xffffffffu, q8, o);
            }
            if (qc == 0) {      // 8 lanes, distinct (R0,R8); slot owner = (ch,ng)
                sSumP[R0*9 + ng] += s0;
                sSqP [R0*9 + ng] += q0;
                sSumP[R8*9 + ng] += s8;
                sSqP [R8*9 + ng] += q8;
            }
        }
        __syncthreads();

        // ---- coalesced copy staging -> gmem (256B per channel row) ----
        {
            const int OY = 4*rt + oyl;
            for (int i = tid; i < CO*16; i += CONV_THREADS) {
                int ch = i >> 4, cu = i & 15;
                uint4 v = *(const uint4*)&sY[ch*SYP + cu*8];
                *(uint4*)(g_yh + ((size_t)(b*CO + ch)*PROWS + OY + 1)*PP + cu*8) = v;
            }
        }
    }

    // ---- block-level stats reduce: one atomic pair per channel ----
    if (tid < 192) {
        float s = 0.f, q = 0.f;
        #pragma unroll
        for (int j = 0; j < 7; ++j) { s += sSumP[tid*9 + j]; q += sSqP[tid*9 + j]; }
        atomicAdd(&g_sum[tid], s);
        atomicAdd(&g_sq [tid], q);
    }
}

// ---------------------------------------------------------------------------
__global__ void finalize_stats_kernel(const float* __restrict__ gamma,
                                      const float* __restrict__ beta) {
    int c = threadIdx.x;
    if (c >= CO) return;
    float invN  = 1.0f / (float)NPC;
    float mean  = g_sum[c] * invN;
    float var   = g_sq[c] * invN - mean*mean;
    float inv   = rsqrtf(var + 1e-5f);
    float scale = gamma[c] * inv;
    g_scale[c]  = scale;
    g_shift[c]  = beta[c] - mean*scale;
    g_sum[c] = 0.f;   // re-zero for next graph replay
    g_sq [c] = 0.f;
}

// ---------------------------------------------------------------------------
// BN + GELU + MaxPool via GELU unimodality:
//   max_w gelu(affine(y)) = max(gelu(affine(min_w y)), gelu(affine(max_w y)))
#define POOL_THREADS 224
#define POOL_SMEM (PROWS*PP*2)     // 28928 B

__global__ __launch_bounds__(POOL_THREADS)
void bn_gelu_pool_kernel(float* __restrict__ out) {
    extern __shared__ __half sH[];
    const int c = blockIdx.x;
    const int b = blockIdx.y;
    const int tid = threadIdx.x;

    const float4* src = (const float4*)(g_yh + ((size_t)(b*CO + c)*PROWS)*PP);
    float4* d4 = (float4*)sH;
    for (int i = tid; i < PROWS*PP/8; i += POOL_THREADS) d4[i] = src[i];
    __syncthreads();

    const float scale = g_scale[c];
    const float shift = g_shift[c];

    const int g  = tid % 14;
    const int ty = tid / 14;
    float* op = &out[(size_t)(b*CO + c)*(PH*PW)];
    for (int py = ty; py < PH; py += 16) {
        const __half2* q0 = (const __half2*)&sH[(2*py)*PP + 8*g + 2];
        const __half2* q1 = (const __half2*)((const __half*)q0 + PP);
        const __half2* q2 = (const __half2*)((const __half*)q1 + PP);
        __half2 vmin[5], vmax[5];
        #pragma unroll
        for (int j = 0; j < 5; ++j) {
            __half2 a = q0[j], bb = q1[j], cc = q2[j];
            vmax[j] = __hmax2(__hmax2(a, bb), cc);
            vmin[j] = __hmin2(__hmin2(a, bb), cc);
        }
        const __half* Hm = (const __half*)vmin;
        const __half* HM = (const __half*)vmax;
        float4 o;
        float* ov = (float*)&o;
        #pragma unroll
        for (int j = 0; j < 4; ++j) {
            __half wm = __hmin(Hm[2*j+1], __hmin(Hm[2*j+2], Hm[2*j+3]));
            __half wM = __hmax(HM[2*j+1], __hmax(HM[2*j+2], HM[2*j+3]));
            float a1 = fmaf(__half2float(wm), scale, shift);
            float a2 = fmaf(__half2float(wM), scale, shift);
            float g1 = 0.5f*a1*(1.0f + erff(a1*0.70710678118654752f));
            float g2 = 0.5f*a2*(1.0f + erff(a2*0.70710678118654752f));
            ov[j] = fmaxf(g1, g2);
        }
        *(float4*)&op[py*PW + 4*g] = o;
    }
}

// ---------------------------------------------------------------------------
extern "C" void kernel_launch(void* const* d_in, const int* in_sizes, int n_in,
                              void* d_out, int out_size) {
    const float* x      = (const float*)d_in[0];
    const float* conv_w = (const float*)d_in[1];
    const float* conv_b = (const float*)d_in[2];
    const float* gamma  = (const float*)d_in[3];
    const float* beta   = (const float*)d_in[4];
    float* out = (float*)d_out;

    cudaFuncSetAttribute(conv_mma_kernel,
                         cudaFuncAttributeMaxDynamicSharedMemorySize, CONV_SMEM);
    cudaFuncSetAttribute(bn_gelu_pool_kernel,
                         cudaFuncAttributeMaxDynamicSharedMemorySize, POOL_SMEM);

    wprep_kernel<<<(CO*32 + 255)/256, 256>>>(conv_w);
    conv_mma_kernel<<<dim3(28, B_), CONV_THREADS, CONV_SMEM>>>(x, conv_b);
    finalize_stats_kernel<<<1, CO>>>(gamma, beta);
    bn_gelu_pool_kernel<<<dim3(CO, B_), POOL_THREADS, POOL_SMEM>>>(out);
}

// round 9
// speedup vs baseline: 1.4459x; 1.1097x over previous
#include <cuda_runtime.h>
#include <cuda_fp16.h>
#include <math.h>
#include <stdint.h>

#define B_    32
#define CIN   3
#define HIN   224
#define WIN   224
#define CO    192
#define OH    112
#define OW    112
#define PH    56
#define PW    56
#define NPC   (B_*OH*OW)   // 401408

// padded y layout: per (b,c) plane = 113 rows x 128 halves.
// row 0 = NaN halo; y row r at row r+1; y col c at col c+4.
// cols 0..3 and 116..127 are NaN halo.
#define PP     128
#define PROWS  113

// -------- device scratch ----------------------------------------------------
__device__ __half g_yh[(size_t)B_*CO*PROWS*PP];   // ~178 MB padded conv output
__device__ __half g_wh[CO*32];                    // fp16 weights, taps 27..31 = 0
__device__ float g_sum[CO];                       // zeroed at load; finalize re-zeroes
__device__ float g_sq[CO];
__device__ float g_scale[CO];
__device__ float g_shift[CO];

// ---------------------------------------------------------------------------
__global__ void wprep_kernel(const float* __restrict__ conv_w) {
    int i = blockIdx.x*256 + threadIdx.x;
    if (i >= CO*32) return;
    int co = i >> 5, k = i & 31;
    float v = (k < 27) ? conv_w[co*27 + k] : 0.f;
    g_wh[i] = __float2half(v);
}

// ---------------------------------------------------------------------------
__device__ __forceinline__ void mma16816(float& d0, float& d1, float& d2, float& d3,
                                         uint32_t a0, uint32_t a1, uint32_t a2, uint32_t a3,
                                         uint32_t b0, uint32_t b1) {
    asm volatile(
        "mma.sync.aligned.m16n8k16.row.col.f32.f16.f16.f32 "
        "{%0,%1,%2,%3},{%4,%5,%6,%7},{%8,%9},{%0,%1,%2,%3};"
        : "+f"(d0), "+f"(d1), "+f"(d2), "+f"(d3)
        : "r"(a0), "r"(a1), "r"(a2), "r"(a3), "r"(b0), "r"(b1));
}

__device__ __forceinline__ void ldsm_x4(uint32_t& r0, uint32_t& r1,
                                        uint32_t& r2, uint32_t& r3, uint32_t p) {
    asm volatile("ldmatrix.sync.aligned.m8n8.x4.shared.b16 {%0,%1,%2,%3},[%4];"
                 : "=r"(r0), "=r"(r1), "=r"(r2), "=r"(r3) : "r"(p));
}

// ---------------------------------------------------------------------------
// Implicit-GEMM conv, 4 output rows per block.
// 448 thr = 14 warps. Warp w: mh=w&1 -> 96 channels, ng=w>>1 -> 16 cols.
// A fragments via ldmatrix.x4; epilogue STS staging -> coalesced STG.128.
// Stats: race-free smem slots, one global atomic/ch per block.
#define CONV_THREADS 448
#define RPB     4
#define XROWS   9
#define XPITCH  232
#define APITCH  40
#define BPITCH  40
#define SYP     136                          // staging pitch (halves)
#define A_OFF   0                            // 192*40  = 7680
#define X_OFF   (CO*APITCH)                  // 3*9*232 = 6264
#define B_OFF   (X_OFF + CIN*XROWS*XPITCH)   // 112*40  = 4480
#define Y_OFF   (B_OFF + OW*BPITCH)          // 192*136 = 26112
#define H_TOT   (Y_OFF + CO*SYP)             // 44536 halves
#define NF      (192 + 2*CO*9)               // bias + sum/sq slots = 3648 floats
#define CONV_SMEM (H_TOT*2 + NF*4)           // 103664 B

__global__ __launch_bounds__(CONV_THREADS, 2)
void conv_mma_kernel(const float* __restrict__ x,
                     const float* __restrict__ conv_b) {
    extern __shared__ __half sm[];
    __half* A_s = sm + A_OFF;
    __half* sX  = sm + X_OFF;
    __half* B_s = sm + B_OFF;
    __half* sY  = sm + Y_OFF;
    float*  sBias = (float*)(sm + H_TOT);
    float*  sSumP = sBias + 192;         // [192][9]
    float*  sSqP  = sSumP + CO*9;        // [192][9]

    const int tid  = threadIdx.x;
    const int lane = tid & 31;
    const int w    = tid >> 5;
    const int rt   = blockIdx.x;    // 4-row tile, 0..27
    const int b    = blockIdx.y;

    if (tid < 192) sBias[tid] = conv_b[tid];
    for (int i = tid; i < CO*9; i += CONV_THREADS) { sSumP[i] = 0.f; sSqP[i] = 0.f; }

    // ---- A: copy prebuilt fp16 weights ----
    {
        const uint32_t* src = (const uint32_t*)g_wh;
        uint32_t* dst = (uint32_t*)A_s;          // pitch 20 uints
        for (int i = tid; i < CO*16; i += CONV_THREADS) {
            int co = i >> 4, ku = i & 15;
            dst[co*20 + ku] = src[i];
        }
    }

    // ---- stage 9 input rows x 3 ci as fp16, cols -1..224 ----
    {
        const int gr_base = 8*rt - 1;
        for (int i = tid; i < CIN*XROWS*226; i += CONV_THREADS) {
            int r9 = i / 226;
            int c  = i - r9*226;
            int ci = r9 / XROWS;
            int r  = r9 - ci*XROWS;
            int gr = gr_base + r;
            int gc = c - 1;
            float v = 0.f;
            if (gr >= 0 && gr < HIN && gc >= 0 && gc < WIN)
                v = x[((size_t)(b*CIN + ci)*HIN + gr)*WIN + gc];
            sX[(ci*XROWS + r)*XPITCH + c] = __float2half(v);
        }
    }

    // ---- staging NaN halo cols (once): cols 0..3 and 116..127 ----
    {
        const __half2 NH2 = __halves2half2(__ushort_as_half((unsigned short)0x7e00),
                                           __ushort_as_half((unsigned short)0x7e00));
        for (int i = tid; i < CO*8; i += CONV_THREADS) {
            int ch = i >> 3, j = i & 7;
            int col = (j < 2) ? 2*j : 116 + 2*(j - 2);
            *(__half2*)&sY[ch*SYP + col] = NH2;
        }
    }

    // ---- top halo row 0 in gmem (rt==0 blocks only) ----
    if (rt == 0) {
        uint4 nv;
        nv.x = nv.y = nv.z = nv.w = 0x7e007e00u;
        for (int i = tid; i < CO*16; i += CONV_THREADS) {
            int ch = i >> 4, cu = i & 15;
            *(uint4*)(g_yh + ((size_t)(b*CO + ch)*PROWS)*PP + cu*8) = nv;
        }
    }
    __syncthreads();

    const int mh = w & 1;
    const int ng = w >> 1;
    const int qr = lane >> 2;
    const int qc = lane & 3;

    // ldmatrix lane pointer base: row = (lane&15), col-half tile = (lane&16)
    const uint32_t a_base = (uint32_t)__cvta_generic_to_shared(A_s)
                          + (uint32_t)((lane & 15) * (APITCH*2))
                          + (uint32_t)((lane & 16) ? 16 : 0)
                          + (uint32_t)(mh ? 6*16*APITCH*2 : 0);

    #pragma unroll 1
    for (int oyl = 0; oyl < RPB; ++oyl) {
        // ---- build B [112 n][40 k]: lane = tap, warp covers 8 n values ----
        {
            int ci = lane / 9;
            int rr = lane - ci*9;
            int ky = rr / 3;
            int kx = rr - ky*3;
            const __half* xs = &sX[(ci*XROWS + 2*oyl + ky)*XPITCH + kx];
            #pragma unroll
            for (int j = 0; j < 8; ++j) {
                int n = w + 14*j;
                __half v = __float2half(0.f);
                if (lane < 27) v = xs[2*n];
                B_s[n*BPITCH + lane] = v;
            }
        }
        __syncthreads();

        // ---- MMA ----
        float acc[6][2][4];
        #pragma unroll
        for (int mi = 0; mi < 6; ++mi)
            #pragma unroll
            for (int ni = 0; ni < 2; ++ni)
                #pragma unroll
                for (int j = 0; j < 4; ++j) acc[mi][ni][j] = 0.f;

        #pragma unroll
        for (int ks = 0; ks < 2; ++ks) {
            const int kb = ks*16 + 2*qc;
            uint32_t bf[2][2];
            #pragma unroll
            for (int ni = 0; ni < 2; ++ni) {
                const __half* bp = &B_s[(ng*16 + ni*8 + qr)*BPITCH + kb];
                bf[ni][0] = *(const uint32_t*)(bp);
                bf[ni][1] = *(const uint32_t*)(bp + 8);
            }
            #pragma unroll
            for (int mi = 0; mi < 6; ++mi) {
                uint32_t a0, a1, a2, a3;
                ldsm_x4(a0, a1, a2, a3,
                        a_base + (uint32_t)(mi*16*APITCH*2 + ks*32));
                #pragma unroll
                for (int ni = 0; ni < 2; ++ni)
                    mma16816(acc[mi][ni][0], acc[mi][ni][1], acc[mi][ni][2], acc[mi][ni][3],
                             a0, a1, a2, a3, bf[ni][0], bf[ni][1]);
            }
        }

        // ---- bias, stats (smem slots), staging STS ----
        #pragma unroll
        for (int mi = 0; mi < 6; ++mi) {
            const int R0 = (mh*6 + mi)*16 + qr;
            const int R8 = R0 + 8;
            const float bias0 = sBias[R0];
            const float bias8 = sBias[R8];
            float s0 = 0.f, q0 = 0.f, s8 = 0.f, q8 = 0.f;
            #pragma unroll
            for (int ni = 0; ni < 2; ++ni) {
                const int C = ng*16 + ni*8 + 2*qc;
                float v0 = acc[mi][ni][0] + bias0;
                float v1 = acc[mi][ni][1] + bias0;
                float v2 = acc[mi][ni][2] + bias8;
                float v3 = acc[mi][ni][3] + bias8;
                *(__half2*)&sY[R0*SYP + 4 + C] = __floats2half2_rn(v0, v1);
                *(__half2*)&sY[R8*SYP + 4 + C] = __floats2half2_rn(v2, v3);
                s0 += v0 + v1;  q0 += v0*v0 + v1*v1;
                s8 += v2 + v3;  q8 += v2*v2 + v3*v3;
            }
            #pragma unroll
            for (int o = 1; o <= 2; o <<= 1) {
                s0 += __shfl_xor_sync(0xffffffffu, s0, o);
                q0 += __shfl_xor_sync(0xffffffffu, q0, o);
                s8 += __shfl_xor_sync(0xffffffffu, s8, o);
                q8 += __shfl_xor_sync(0xffffffffu, q8, o);
            }
            if (qc == 0) {
                sSumP[R0*9 + ng] += s0;
                sSqP [R0*9 + ng] += q0;
                sSumP[R8*9 + ng] += s8;
                sSqP [R8*9 + ng] += q8;
            }
        }
        __syncthreads();

        // ---- coalesced copy staging -> gmem (256B per channel row) ----
        {
            const int OY = 4*rt + oyl;
            for (int i = tid; i < CO*16; i += CONV_THREADS) {
                int ch = i >> 4, cu = i & 15;
                uint4 v = *(const uint4*)&sY[ch*SYP + cu*8];
                *(uint4*)(g_yh + ((size_t)(b*CO + ch)*PROWS + OY + 1)*PP + cu*8) = v;
            }
        }
    }

    // ---- block-level stats reduce: one atomic pair per channel ----
    if (tid < 192) {
        float s = 0.f, q = 0.f;
        #pragma unroll
        for (int j = 0; j < 7; ++j) { s += sSumP[tid*9 + j]; q += sSqP[tid*9 + j]; }
        atomicAdd(&g_sum[tid], s);
        atomicAdd(&g_sq [tid], q);
    }
}

// ---------------------------------------------------------------------------
__global__ void finalize_stats_kernel(const float* __restrict__ gamma,
                                      const float* __restrict__ beta) {
    int c = threadIdx.x;
    if (c >= CO) return;
    float invN  = 1.0f / (float)NPC;
    float mean  = g_sum[c] * invN;
    float var   = g_sq[c] * invN - mean*mean;
    float inv   = rsqrtf(var + 1e-5f);
    float scale = gamma[c] * inv;
    g_scale[c]  = scale;
    g_shift[c]  = beta[c] - mean*scale;
    g_sum[c] = 0.f;   // re-zero for next graph replay
    g_sq [c] = 0.f;
}

// ---------------------------------------------------------------------------
// BN + GELU + MaxPool via GELU unimodality, with the hi>=0 fast path:
//   hi >= 0  =>  gelu(lo) <= 0 <= gelu(hi)  =>  answer = gelu(hi) (1 erf).
#define POOL_THREADS 224
#define POOL_SMEM (PROWS*PP*2)     // 28928 B

__global__ __launch_bounds__(POOL_THREADS)
void bn_gelu_pool_kernel(float* __restrict__ out) {
    extern __shared__ __half sH[];
    const int c = blockIdx.x;
    const int b = blockIdx.y;
    const int tid = threadIdx.x;

    const float4* src = (const float4*)(g_yh + ((size_t)(b*CO + c)*PROWS)*PP);
    float4* d4 = (float4*)sH;
    for (int i = tid; i < PROWS*PP/8; i += POOL_THREADS) d4[i] = src[i];
    __syncthreads();

    const float scale = g_scale[c];
    const float shift = g_shift[c];

    const int g  = tid % 14;
    const int ty = tid / 14;
    float* op = &out[(size_t)(b*CO + c)*(PH*PW)];
    for (int py = ty; py < PH; py += 16) {
        const __half2* q0 = (const __half2*)&sH[(2*py)*PP + 8*g + 2];
        const __half2* q1 = (const __half2*)((const __half*)q0 + PP);
        const __half2* q2 = (const __half2*)((const __half*)q1 + PP);
        __half2 vmin[5], vmax[5];
        #pragma unroll
        for (int j = 0; j < 5; ++j) {
            __half2 a = q0[j], bb = q1[j], cc = q2[j];
            vmax[j] = __hmax2(__hmax2(a, bb), cc);
            vmin[j] = __hmin2(__hmin2(a, bb), cc);
        }
        const __half* Hm = (const __half*)vmin;
        const __half* HM = (const __half*)vmax;
        float4 o;
        float* ov = (float*)&o;
        #pragma unroll
        for (int j = 0; j < 4; ++j) {
            __half wm = __hmin(Hm[2*j+1], __hmin(Hm[2*j+2], Hm[2*j+3]));
            __half wM = __hmax(HM[2*j+1], __hmax(HM[2*j+2], HM[2*j+3]));
            float a1 = fmaf(__half2float(wm), scale, shift);
            float a2 = fmaf(__half2float(wM), scale, shift);
            float lo = fminf(a1, a2);
            float hi = fmaxf(a1, a2);
            float r  = 0.5f*hi*(1.0f + erff(hi*0.70710678118654752f));
            if (hi < 0.f) {   // rare (~0.2%): window entirely negative
                float gl = 0.5f*lo*(1.0f + erff(lo*0.70710678118654752f));
                r = fmaxf(r, gl);
            }
            ov[j] = r;
        }
        *(float4*)&op[py*PW + 4*g] = o;
    }
}

// ---------------------------------------------------------------------------
extern "C" void kernel_launch(void* const* d_in, const int* in_sizes, int n_in,
                              void* d_out, int out_size) {
    const float* x      = (const float*)d_in[0];
    const float* conv_w = (const float*)d_in[1];
    const float* conv_b = (const float*)d_in[2];
    const float* gamma  = (const float*)d_in[3];
    const float* beta   = (const float*)d_in[4];
    float* out = (float*)d_out;

    cudaFuncSetAttribute(conv_mma_kernel,
                         cudaFuncAttributeMaxDynamicSharedMemorySize, CONV_SMEM);
    cudaFuncSetAttribute(bn_gelu_pool_kernel,
                         cudaFuncAttributeMaxDynamicSharedMemorySize, POOL_SMEM);

    wprep_kernel<<<(CO*32 + 255)/256, 256>>>(conv_w);
    conv_mma_kernel<<<dim3(28, B_), CONV_THREADS, CONV_SMEM>>>(x, conv_b);
    finalize_stats_kernel<<<1, CO>>>(gamma, beta);
    bn_gelu_pool_kernel<<<dim3(CO, B_), POOL_THREADS, POOL_SMEM>>>(out);
}

// round 10
// speedup vs baseline: 1.5590x; 1.0783x over previous
#include <cuda_runtime.h>
#include <cuda_fp16.h>
#include <math.h>
#include <stdint.h>

#define B_    32
#define CIN   3
#define HIN   224
#define WIN   224
#define CO    192
#define OH    112
#define OW    112
#define PH    56
#define PW    56
#define NPC   (B_*OH*OW)   // 401408

// padded y layout: per (b,c) plane = 113 rows x 128 halves.
// row 0 = NaN halo; y row r at row r+1; y col c at col c+4.
// cols 0..3 and 116..127 are NaN halo.
#define PP     128
#define PROWS  113

// -------- device scratch ----------------------------------------------------
__device__ __half g_yh[(size_t)B_*CO*PROWS*PP];   // ~178 MB padded conv output
__device__ __half g_wh[CO*32];                    // fp16 weights, taps 27..31 = 0
__device__ float g_sum[CO];                       // zeroed at load; finalize re-zeroes
__device__ float g_sq[CO];
__device__ float g_scale[CO];
__device__ float g_shift[CO];

// ---------------------------------------------------------------------------
__global__ void wprep_kernel(const float* __restrict__ conv_w) {
    int i = blockIdx.x*256 + threadIdx.x;
    if (i >= CO*32) return;
    int co = i >> 5, k = i & 31;
    float v = (k < 27) ? conv_w[co*27 + k] : 0.f;
    g_wh[i] = __float2half(v);
}

// ---------------------------------------------------------------------------
__device__ __forceinline__ void mma16816(float& d0, float& d1, float& d2, float& d3,
                                         uint32_t a0, uint32_t a1, uint32_t a2, uint32_t a3,
                                         uint32_t b0, uint32_t b1) {
    asm volatile(
        "mma.sync.aligned.m16n8k16.row.col.f32.f16.f16.f32 "
        "{%0,%1,%2,%3},{%4,%5,%6,%7},{%8,%9},{%0,%1,%2,%3};"
        : "+f"(d0), "+f"(d1), "+f"(d2), "+f"(d3)
        : "r"(a0), "r"(a1), "r"(a2), "r"(a3), "r"(b0), "r"(b1));
}

__device__ __forceinline__ void ldsm_x4(uint32_t& r0, uint32_t& r1,
                                        uint32_t& r2, uint32_t& r3, uint32_t p) {
    asm volatile("ldmatrix.sync.aligned.m8n8.x4.shared.b16 {%0,%1,%2,%3},[%4];"
                 : "=r"(r0), "=r"(r1), "=r"(r2), "=r"(r3) : "r"(p));
}

// ---------------------------------------------------------------------------
// Implicit-GEMM conv, 2 output rows per block (finer grid -> smaller tail).
// 448 thr = 14 warps. Warp w: mh=w&1 -> 96 channels, ng=w>>1 -> 16 cols.
#define CONV_THREADS 448
#define RPB     2
#define XROWS   5
#define XPITCH  232
#define APITCH  40
#define BPITCH  40
#define SYP     136                          // staging pitch (halves)
#define A_OFF   0                            // 192*40  = 7680
#define X_OFF   (CO*APITCH)                  // 3*5*232 = 3480
#define B_OFF   (X_OFF + CIN*XROWS*XPITCH)   // 112*40  = 4480
#define Y_OFF   (B_OFF + OW*BPITCH)          // 192*136 = 26112
#define H_TOT   (Y_OFF + CO*SYP)             // 41752 halves
#define NF      (192 + 2*CO*9)               // bias + sum/sq slots = 3648 floats
#define CONV_SMEM (H_TOT*2 + NF*4)           // 83504 + 14592 = 98096 B

__global__ __launch_bounds__(CONV_THREADS, 2)
void conv_mma_kernel(const float* __restrict__ x,
                     const float* __restrict__ conv_b) {
    extern __shared__ __half sm[];
    __half* A_s = sm + A_OFF;
    __half* sX  = sm + X_OFF;
    __half* B_s = sm + B_OFF;
    __half* sY  = sm + Y_OFF;
    float*  sBias = (float*)(sm + H_TOT);
    float*  sSumP = sBias + 192;         // [192][9]
    float*  sSqP  = sSumP + CO*9;        // [192][9]

    const int tid  = threadIdx.x;
    const int lane = tid & 31;
    const int w    = tid >> 5;
    const int rt   = blockIdx.x;    // 2-row tile, 0..55
    const int b    = blockIdx.y;

    if (tid < 192) sBias[tid] = conv_b[tid];
    for (int i = tid; i < CO*9; i += CONV_THREADS) { sSumP[i] = 0.f; sSqP[i] = 0.f; }

    // ---- A: copy prebuilt fp16 weights ----
    {
        const uint32_t* src = (const uint32_t*)g_wh;
        uint32_t* dst = (uint32_t*)A_s;          // pitch 20 uints
        for (int i = tid; i < CO*16; i += CONV_THREADS) {
            int co = i >> 4, ku = i & 15;
            dst[co*20 + ku] = src[i];
        }
    }

    // ---- stage 5 input rows x 3 ci as fp16, cols -1..224 ----
    {
        const int gr_base = 4*rt - 1;
        for (int i = tid; i < CIN*XROWS*226; i += CONV_THREADS) {
            int r9 = i / 226;
            int c  = i - r9*226;
            int ci = r9 / XROWS;
            int r  = r9 - ci*XROWS;
            int gr = gr_base + r;
            int gc = c - 1;
            float v = 0.f;
            if (gr >= 0 && gr < HIN && gc >= 0 && gc < WIN)
                v = x[((size_t)(b*CIN + ci)*HIN + gr)*WIN + gc];
            sX[(ci*XROWS + r)*XPITCH + c] = __float2half(v);
        }
    }

    // ---- staging NaN halo cols (once): cols 0..3 and 116..127 ----
    {
        const __half2 NH2 = __halves2half2(__ushort_as_half((unsigned short)0x7e00),
                                           __ushort_as_half((unsigned short)0x7e00));
        for (int i = tid; i < CO*8; i += CONV_THREADS) {
            int ch = i >> 3, j = i & 7;
            int col = (j < 2) ? 2*j : 116 + 2*(j - 2);
            *(__half2*)&sY[ch*SYP + col] = NH2;
        }
    }

    // ---- top halo row 0 in gmem (rt==0 blocks only) ----
    if (rt == 0) {
        uint4 nv;
        nv.x = nv.y = nv.z = nv.w = 0x7e007e00u;
        for (int i = tid; i < CO*16; i += CONV_THREADS) {
            int ch = i >> 4, cu = i & 15;
            *(uint4*)(g_yh + ((size_t)(b*CO + ch)*PROWS)*PP + cu*8) = nv;
        }
    }
    __syncthreads();

    const int mh = w & 1;
    const int ng = w >> 1;
    const int qr = lane >> 2;
    const int qc = lane & 3;

    const uint32_t a_base = (uint32_t)__cvta_generic_to_shared(A_s)
                          + (uint32_t)((lane & 15) * (APITCH*2))
                          + (uint32_t)((lane & 16) ? 16 : 0)
                          + (uint32_t)(mh ? 6*16*APITCH*2 : 0);

    #pragma unroll 1
    for (int oyl = 0; oyl < RPB; ++oyl) {
        // ---- build B [112 n][40 k]: lane = tap, warp covers 8 n values ----
        {
            int ci = lane / 9;
            int rr = lane - ci*9;
            int ky = rr / 3;
            int kx = rr - ky*3;
            const __half* xs = &sX[(ci*XROWS + 2*oyl + ky)*XPITCH + kx];
            #pragma unroll
            for (int j = 0; j < 8; ++j) {
                int n = w + 14*j;
                __half v = __float2half(0.f);
                if (lane < 27) v = xs[2*n];
                B_s[n*BPITCH + lane] = v;
            }
        }
        __syncthreads();

        // ---- MMA ----
        float acc[6][2][4];
        #pragma unroll
        for (int mi = 0; mi < 6; ++mi)
            #pragma unroll
            for (int ni = 0; ni < 2; ++ni)
                #pragma unroll
                for (int j = 0; j < 4; ++j) acc[mi][ni][j] = 0.f;

        #pragma unroll
        for (int ks = 0; ks < 2; ++ks) {
            const int kb = ks*16 + 2*qc;
            uint32_t bf[2][2];
            #pragma unroll
            for (int ni = 0; ni < 2; ++ni) {
                const __half* bp = &B_s[(ng*16 + ni*8 + qr)*BPITCH + kb];
                bf[ni][0] = *(const uint32_t*)(bp);
                bf[ni][1] = *(const uint32_t*)(bp + 8);
            }
            #pragma unroll
            for (int mi = 0; mi < 6; ++mi) {
                uint32_t a0, a1, a2, a3;
                ldsm_x4(a0, a1, a2, a3,
                        a_base + (uint32_t)(mi*16*APITCH*2 + ks*32));
                #pragma unroll
                for (int ni = 0; ni < 2; ++ni)
                    mma16816(acc[mi][ni][0], acc[mi][ni][1], acc[mi][ni][2], acc[mi][ni][3],
                             a0, a1, a2, a3, bf[ni][0], bf[ni][1]);
            }
        }

        // ---- bias, stats (smem slots), staging STS ----
        #pragma unroll
        for (int mi = 0; mi < 6; ++mi) {
            const int R0 = (mh*6 + mi)*16 + qr;
            const int R8 = R0 + 8;
            const float bias0 = sBias[R0];
            const float bias8 = sBias[R8];
            float s0 = 0.f, q0 = 0.f, s8 = 0.f, q8 = 0.f;
            #pragma unroll
            for (int ni = 0; ni < 2; ++ni) {
                const int C = ng*16 + ni*8 + 2*qc;
                float v0 = acc[mi][ni][0] + bias0;
                float v1 = acc[mi][ni][1] + bias0;
                float v2 = acc[mi][ni][2] + bias8;
                float v3 = acc[mi][ni][3] + bias8;
                *(__half2*)&sY[R0*SYP + 4 + C] = __floats2half2_rn(v0, v1);
                *(__half2*)&sY[R8*SYP + 4 + C] = __floats2half2_rn(v2, v3);
                s0 += v0 + v1;  q0 += v0*v0 + v1*v1;
                s8 += v2 + v3;  q8 += v2*v2 + v3*v3;
            }
            #pragma unroll
            for (int o = 1; o <= 2; o <<= 1) {
                s0 += __shfl_xor_sync(0xffffffffu, s0, o);
                q0 += __shfl_xor_sync(0xffffffffu, q0, o);
                s8 += __shfl_xor_sync(0xffffffffu, s8, o);
                q8 += __shfl_xor_sync(0xffffffffu, q8, o);
            }
            if (qc == 0) {
                sSumP[R0*9 + ng] += s0;
                sSqP [R0*9 + ng] += q0;
                sSumP[R8*9 + ng] += s8;
                sSqP [R8*9 + ng] += q8;
            }
        }
        __syncthreads();

        // ---- coalesced copy staging -> gmem (256B per channel row) ----
        {
            const int OY = 2*rt + oyl;
            for (int i = tid; i < CO*16; i += CONV_THREADS) {
                int ch = i >> 4, cu = i & 15;
                uint4 v = *(const uint4*)&sY[ch*SYP + cu*8];
                *(uint4*)(g_yh + ((size_t)(b*CO + ch)*PROWS + OY + 1)*PP + cu*8) = v;
            }
        }
    }

    // ---- block-level stats reduce: one atomic pair per channel ----
    if (tid < 192) {
        float s = 0.f, q = 0.f;
        #pragma unroll
        for (int j = 0; j < 7; ++j) { s += sSumP[tid*9 + j]; q += sSqP[tid*9 + j]; }
        atomicAdd(&g_sum[tid], s);
        atomicAdd(&g_sq [tid], q);
    }
}

// ---------------------------------------------------------------------------
__global__ void finalize_stats_kernel(const float* __restrict__ gamma,
                                      const float* __restrict__ beta) {
    int c = threadIdx.x;
    if (c >= CO) return;
    float invN  = 1.0f / (float)NPC;
    float mean  = g_sum[c] * invN;
    float var   = g_sq[c] * invN - mean*mean;
    float inv   = rsqrtf(var + 1e-5f);
    float scale = gamma[c] * inv;
    g_scale[c]  = scale;
    g_shift[c]  = beta[c] - mean*scale;
    g_sum[c] = 0.f;   // re-zero for next graph replay
    g_sq [c] = 0.f;
}

// ---------------------------------------------------------------------------
// BN + GELU + MaxPool, DIRECT from padded gmem (no smem staging):
// thread -> 4 pooled outputs; loads 3 rows x 16 halves (aligned uint4 pairs);
// NaN halo makes hmin/hmax drop padding. GELU-unimodality + hi>=0 fast path.
#define POOL_THREADS 256
#define POOL_GROUPS  (B_*CO*PH*PW/4)   // 4,816,896 -> 18816 blocks

__global__ __launch_bounds__(POOL_THREADS)
void bn_gelu_pool_kernel(float* __restrict__ out) {
    const int idx = blockIdx.x*POOL_THREADS + threadIdx.x;
    const int q   = idx << 2;            // first output index of this group
    const int px  = q % PW;              // multiple of 4
    const int t1  = q / PW;
    const int py  = t1 % PH;
    const int t2  = t1 / PH;             // b*CO + ch
    const int ch  = t2 % CO;

    const float scale = g_scale[ch];
    const float shift = g_shift[ch];

    const __half* base = g_yh + (size_t)t2*(PROWS*PP) + (size_t)(2*py)*PP + 2*px;

    union U { uint4 v[2]; __half2 h[8]; } R0, R1, R2;
    R0.v[0] = *(const uint4*)(base);
    R0.v[1] = *(const uint4*)(base + 8);
    R1.v[0] = *(const uint4*)(base + PP);
    R1.v[1] = *(const uint4*)(base + PP + 8);
    R2.v[0] = *(const uint4*)(base + 2*PP);
    R2.v[1] = *(const uint4*)(base + 2*PP + 8);

    __half2 vmin[8], vmax[8];
    #pragma unroll
    for (int j = 0; j < 8; ++j) {
        vmax[j] = __hmax2(__hmax2(R0.h[j], R1.h[j]), R2.h[j]);
        vmin[j] = __hmin2(__hmin2(R0.h[j], R1.h[j]), R2.h[j]);
    }
    const __half* Hm = (const __half*)vmin;
    const __half* HM = (const __half*)vmax;

    float4 o;
    float* ov = (float*)&o;
    #pragma unroll
    for (int j = 0; j < 4; ++j) {
        // window for output px+j covers padded positions 2j+3 .. 2j+5
        __half wm = __hmin(Hm[2*j+3], __hmin(Hm[2*j+4], Hm[2*j+5]));
        __half wM = __hmax(HM[2*j+3], __hmax(HM[2*j+4], HM[2*j+5]));
        float a1 = fmaf(__half2float(wm), scale, shift);
        float a2 = fmaf(__half2float(wM), scale, shift);
        float lo = fminf(a1, a2);
        float hi = fmaxf(a1, a2);
        float r  = 0.5f*hi*(1.0f + erff(hi*0.70710678118654752f));
        if (hi < 0.f) {   // rare: window entirely negative
            float gl = 0.5f*lo*(1.0f + erff(lo*0.70710678118654752f));
            r = fmaxf(r, gl);
        }
        ov[j] = r;
    }
    *(float4*)&out[(size_t)(t2*PH + py)*PW + px] = o;
}

// ---------------------------------------------------------------------------
extern "C" void kernel_launch(void* const* d_in, const int* in_sizes, int n_in,
                              void* d_out, int out_size) {
    const float* x      = (const float*)d_in[0];
    const float* conv_w = (const float*)d_in[1];
    const float* conv_b = (const float*)d_in[2];
    const float* gamma  = (const float*)d_in[3];
    const float* beta   = (const float*)d_in[4];
    float* out = (float*)d_out;

    cudaFuncSetAttribute(conv_mma_kernel,
                         cudaFuncAttributeMaxDynamicSharedMemorySize, CONV_SMEM);

    wprep_kernel<<<(CO*32 + 255)/256, 256>>>(conv_w);
    conv_mma_kernel<<<dim3(56, B_), CONV_THREADS, CONV_SMEM>>>(x, conv_b);
    finalize_stats_kernel<<<1, CO>>>(gamma, beta);
    bn_gelu_pool_kernel<<<POOL_GROUPS/POOL_THREADS, POOL_THREADS>>>(out);
}

// round 11
// speedup vs baseline: 1.7542x; 1.1252x over previous
#include <cuda_runtime.h>
#include <cuda_fp16.h>
#include <math.h>
#include <stdint.h>

#define B_    32
#define CIN   3
#define HIN   224
#define WIN   224
#define CO    192
#define OH    112
#define OW    112
#define PH    56
#define PW    56
#define NPC   (B_*OH*OW)   // 401408

// padded y layout: per (b,c) plane = 113 rows x 128 halves.
// row 0 = NaN halo; y row r at row r+1; y col c at col c+4.
#define PP     128
#define PROWS  113

// -------- device scratch ----------------------------------------------------
__device__ __half g_yh[(size_t)B_*CO*PROWS*PP];   // ~178 MB padded conv output
__device__ __half g_wh[CO*32];                    // fp16 weights, taps 27..31 = 0
__device__ float g_sum[CO];                       // zeroed at load; finalize re-zeroes
__device__ float g_sq[CO];
__device__ float g_scale[CO];
__device__ float g_shift[CO];

// ---------------------------------------------------------------------------
__global__ void wprep_kernel(const float* __restrict__ conv_w) {
    int i = blockIdx.x*256 + threadIdx.x;
    if (i >= CO*32) return;
    int co = i >> 5, k = i & 31;
    float v = (k < 27) ? conv_w[co*27 + k] : 0.f;
    g_wh[i] = __float2half(v);
}

// ---------------------------------------------------------------------------
__device__ __forceinline__ void mma16816(float& d0, float& d1, float& d2, float& d3,
                                         uint32_t a0, uint32_t a1, uint32_t a2, uint32_t a3,
                                         uint32_t b0, uint32_t b1) {
    asm volatile(
        "mma.sync.aligned.m16n8k16.row.col.f32.f16.f16.f32 "
        "{%0,%1,%2,%3},{%4,%5,%6,%7},{%8,%9},{%0,%1,%2,%3};"
        : "+f"(d0), "+f"(d1), "+f"(d2), "+f"(d3)
        : "r"(a0), "r"(a1), "r"(a2), "r"(a3), "r"(b0), "r"(b1));
}

__device__ __forceinline__ void ldsm_x4(uint32_t& r0, uint32_t& r1,
                                        uint32_t& r2, uint32_t& r3, uint32_t p) {
    asm volatile("ldmatrix.sync.aligned.m8n8.x4.shared.b16 {%0,%1,%2,%3},[%4];"
                 : "=r"(r0), "=r"(r1), "=r"(r2), "=r"(r3) : "r"(p));
}

// ---------------------------------------------------------------------------
// Implicit-GEMM conv, 2 output rows per block.
// 448 thr = 14 warps. Warp w: mh=w&1 -> 96 channels, ng=w>>1 -> 16 cols.
// Staging: warp-per-(ci,row), coalesced LDG.128, no div/mod in the hot loop.
// sX layout: col = gc + 2 (cols 0..1 left pad, 2..225 data).
#define CONV_THREADS 448
#define RPB     2
#define XROWS   5
#define XPITCH  232
#define APITCH  40
#define BPITCH  40
#define SYP     136                          // staging pitch (halves)
#define A_OFF   0                            // 192*40  = 7680
#define X_OFF   (CO*APITCH)                  // 15*232  = 3480
#define B_OFF   (X_OFF + CIN*XROWS*XPITCH)   // 112*40  = 4480
#define Y_OFF   (B_OFF + OW*BPITCH)          // 192*136 = 26112
#define H_TOT   (Y_OFF + CO*SYP)             // 41752 halves
#define NF      (192 + 2*CO*7)               // bias + sum/sq slots = 2880 floats
#define CONV_SMEM (H_TOT*2 + NF*4)           // 83504 + 11520 = 95024 B

__global__ __launch_bounds__(CONV_THREADS, 2)
void conv_mma_kernel(const float* __restrict__ x,
                     const float* __restrict__ conv_b) {
    extern __shared__ __half sm[];
    __half* A_s = sm + A_OFF;
    __half* sX  = sm + X_OFF;
    __half* B_s = sm + B_OFF;
    __half* sY  = sm + Y_OFF;
    float*  sBias = (float*)(sm + H_TOT);
    float*  sSumP = sBias + 192;         // [192][7]
    float*  sSqP  = sSumP + CO*7;        // [192][7]

    const int tid  = threadIdx.x;
    const int lane = tid & 31;
    const int w    = tid >> 5;
    const int rt   = blockIdx.x;    // 2-row tile, 0..55
    const int b    = blockIdx.y;

    if (tid < 192) sBias[tid] = conv_b[tid];
    for (int i = tid; i < CO*7; i += CONV_THREADS) { sSumP[i] = 0.f; sSqP[i] = 0.f; }

    // ---- A: copy prebuilt fp16 weights ----
    {
        const uint32_t* src = (const uint32_t*)g_wh;
        uint32_t* dst = (uint32_t*)A_s;          // pitch 20 uints
        for (int i = tid; i < CO*16; i += CONV_THREADS) {
            int co = i >> 4, ku = i & 15;
            dst[co*20 + ku] = src[i];
        }
    }

    // ---- stage 5 rows x 3 ci, coalesced: warp -> (ci,row) pair ----
    for (int pair = w; pair < CIN*XROWS; pair += 14) {
        int ci = pair / XROWS;
        int r  = pair - ci*XROWS;
        int gr = 4*rt - 1 + r;
        __half* row = &sX[pair*XPITCH];
        if (gr < 0 || gr >= HIN) {
            if (lane < 29) *(uint4*)&row[8*lane] = make_uint4(0,0,0,0);
        } else {
            const float4* xb = (const float4*)(x + ((size_t)(b*CIN + ci)*HIN + gr)*WIN);
            float4 a = xb[lane];                       // gc 4l..4l+3
            *(__half2*)&row[2 + 4*lane]     = __floats2half2_rn(a.x, a.y);
            *(__half2*)&row[2 + 4*lane + 2] = __floats2half2_rn(a.z, a.w);
            if (lane < 24) {
                float4 c4 = xb[lane + 32];             // gc 128+4l..
                *(__half2*)&row[2 + 4*(lane+32)]     = __floats2half2_rn(c4.x, c4.y);
                *(__half2*)&row[2 + 4*(lane+32) + 2] = __floats2half2_rn(c4.z, c4.w);
            } else if (lane == 24) {
                *(__half2*)&row[0] = __floats2half2_rn(0.f, 0.f);   // cols 0..1 pad
            }
        }
    }

    // ---- staging NaN halo cols (once): cols 0..3 and 116..127 of sY ----
    {
        const __half2 NH2 = __halves2half2(__ushort_as_half((unsigned short)0x7e00),
                                           __ushort_as_half((unsigned short)0x7e00));
        for (int i = tid; i < CO*8; i += CONV_THREADS) {
            int ch = i >> 3, j = i & 7;
            int col = (j < 2) ? 2*j : 116 + 2*(j - 2);
            *(__half2*)&sY[ch*SYP + col] = NH2;
        }
    }

    // ---- top halo row 0 in gmem (rt==0 blocks only) ----
    if (rt == 0) {
        uint4 nv;
        nv.x = nv.y = nv.z = nv.w = 0x7e007e00u;
        for (int i = tid; i < CO*16; i += CONV_THREADS) {
            int ch = i >> 4, cu = i & 15;
            *(uint4*)(g_yh + ((size_t)(b*CO + ch)*PROWS)*PP + cu*8) = nv;
        }
    }
    __syncthreads();

    const int mh = w & 1;
    const int ng = w >> 1;
    const int qr = lane >> 2;
    const int qc = lane & 3;

    const uint32_t a_base = (uint32_t)__cvta_generic_to_shared(A_s)
                          + (uint32_t)((lane & 15) * (APITCH*2))
                          + (uint32_t)((lane & 16) ? 16 : 0)
                          + (uint32_t)(mh ? 6*16*APITCH*2 : 0);

    #pragma unroll 1
    for (int oyl = 0; oyl < RPB; ++oyl) {
        // ---- build B [112 n][40 k]: lane = tap, warp covers 8 n values ----
        {
            int ci = lane / 9;
            int rr = lane - ci*9;
            int ky = rr / 3;
            int kx = rr - ky*3;
            // sX col = gc + 2; gc = 2n + kx - 1 -> col = 2n + kx + 1
            const __half* xs = &sX[(ci*XROWS + 2*oyl + ky)*XPITCH + kx + 1];
            #pragma unroll
            for (int j = 0; j < 8; ++j) {
                int n = w + 14*j;
                __half v = __float2half(0.f);
                if (lane < 27) v = xs[2*n];
                B_s[n*BPITCH + lane] = v;
            }
        }
        __syncthreads();

        // ---- MMA ----
        float acc[6][2][4];
        #pragma unroll
        for (int mi = 0; mi < 6; ++mi)
            #pragma unroll
            for (int ni = 0; ni < 2; ++ni)
                #pragma unroll
                for (int j = 0; j < 4; ++j) acc[mi][ni][j] = 0.f;

        #pragma unroll
        for (int ks = 0; ks < 2; ++ks) {
            const int kb = ks*16 + 2*qc;
            uint32_t bf[2][2];
            #pragma unroll
            for (int ni = 0; ni < 2; ++ni) {
                const __half* bp = &B_s[(ng*16 + ni*8 + qr)*BPITCH + kb];
                bf[ni][0] = *(const uint32_t*)(bp);
                bf[ni][1] = *(const uint32_t*)(bp + 8);
            }
            #pragma unroll
            for (int mi = 0; mi < 6; ++mi) {
                uint32_t a0, a1, a2, a3;
                ldsm_x4(a0, a1, a2, a3,
                        a_base + (uint32_t)(mi*16*APITCH*2 + ks*32));
                #pragma unroll
                for (int ni = 0; ni < 2; ++ni)
                    mma16816(acc[mi][ni][0], acc[mi][ni][1], acc[mi][ni][2], acc[mi][ni][3],
                             a0, a1, a2, a3, bf[ni][0], bf[ni][1]);
            }
        }

        // ---- bias, stats (smem slots), staging STS ----
        #pragma unroll
        for (int mi = 0; mi < 6; ++mi) {
            const int R0 = (mh*6 + mi)*16 + qr;
            const int R8 = R0 + 8;
            const float bias0 = sBias[R0];
            const float bias8 = sBias[R8];
            float s0 = 0.f, q0 = 0.f, s8 = 0.f, q8 = 0.f;
            #pragma unroll
            for (int ni = 0; ni < 2; ++ni) {
                const int C = ng*16 + ni*8 + 2*qc;
                float v0 = acc[mi][ni][0] + bias0;
                float v1 = acc[mi][ni][1] + bias0;
                float v2 = acc[mi][ni][2] + bias8;
                float v3 = acc[mi][ni][3] + bias8;
                *(__half2*)&sY[R0*SYP + 4 + C] = __floats2half2_rn(v0, v1);
                *(__half2*)&sY[R8*SYP + 4 + C] = __floats2half2_rn(v2, v3);
                s0 += v0 + v1;  q0 += v0*v0 + v1*v1;
                s8 += v2 + v3;  q8 += v2*v2 + v3*v3;
            }
            #pragma unroll
            for (int o = 1; o <= 2; o <<= 1) {
                s0 += __shfl_xor_sync(0xffffffffu, s0, o);
                q0 += __shfl_xor_sync(0xffffffffu, q0, o);
                s8 += __shfl_xor_sync(0xffffffffu, s8, o);
                q8 += __shfl_xor_sync(0xffffffffu, q8, o);
            }
            if (qc == 0) {
                sSumP[R0*7 + ng] += s0;
                sSqP [R0*7 + ng] += q0;
                sSumP[R8*7 + ng] += s8;
                sSqP [R8*7 + ng] += q8;
            }
        }
        __syncthreads();

        // ---- coalesced copy staging -> gmem (256B per channel row) ----
        {
            const int OY = 2*rt + oyl;
            for (int i = tid; i < CO*16; i += CONV_THREADS) {
                int ch = i >> 4, cu = i & 15;
                uint4 v = *(const uint4*)&sY[ch*SYP + cu*8];
                *(uint4*)(g_yh + ((size_t)(b*CO + ch)*PROWS + OY + 1)*PP + cu*8) = v;
            }
        }
    }

    // ---- block-level stats reduce: one atomic pair per channel ----
    if (tid < 192) {
        float s = 0.f, q = 0.f;
        #pragma unroll
        for (int j = 0; j < 7; ++j) { s += sSumP[tid*7 + j]; q += sSqP[tid*7 + j]; }
        atomicAdd(&g_sum[tid], s);
        atomicAdd(&g_sq [tid], q);
    }
}

// ---------------------------------------------------------------------------
__global__ void finalize_stats_kernel(const float* __restrict__ gamma,
                                      const float* __restrict__ beta) {
    int c = threadIdx.x;
    if (c >= CO) return;
    float invN  = 1.0f / (float)NPC;
    float mean  = g_sum[c] * invN;
    float var   = g_sq[c] * invN - mean*mean;
    float inv   = rsqrtf(var + 1e-5f);
    float scale = gamma[c] * inv;
    g_scale[c]  = scale;
    g_shift[c]  = beta[c] - mean*scale;
    g_sum[c] = 0.f;   // re-zero for next graph replay
    g_sq [c] = 0.f;
}

// ---------------------------------------------------------------------------
// BN + GELU + MaxPool, direct from padded gmem.
#define POOL_THREADS 256
#define POOL_GROUPS  (B_*CO*PH*PW/4)   // 18816 blocks

__global__ __launch_bounds__(POOL_THREADS)
void bn_gelu_pool_kernel(float* __restrict__ out) {
    const int idx = blockIdx.x*POOL_THREADS + threadIdx.x;
    const int q   = idx << 2;
    const int px  = q % PW;
    const int t1  = q / PW;
    const int py  = t1 % PH;
    const int t2  = t1 / PH;             // b*CO + ch
    const int ch  = t2 % CO;

    const float scale = g_scale[ch];
    const float shift = g_shift[ch];

    const __half* base = g_yh + (size_t)t2*(PROWS*PP) + (size_t)(2*py)*PP + 2*px;

    union U { uint4 v[2]; __half2 h[8]; } R0, R1, R2;
    R0.v[0] = *(const uint4*)(base);
    R0.v[1] = *(const uint4*)(base + 8);
    R1.v[0] = *(const uint4*)(base + PP);
    R1.v[1] = *(const uint4*)(base + PP + 8);
    R2.v[0] = *(const uint4*)(base + 2*PP);
    R2.v[1] = *(const uint4*)(base + 2*PP + 8);

    __half2 vmin[8], vmax[8];
    #pragma unroll
    for (int j = 0; j < 8; ++j) {
        vmax[j] = __hmax2(__hmax2(R0.h[j], R1.h[j]), R2.h[j]);
        vmin[j] = __hmin2(__hmin2(R0.h[j], R1.h[j]), R2.h[j]);
    }
    const __half* Hm = (const __half*)vmin;
    const __half* HM = (const __half*)vmax;

    float4 o;
    float* ov = (float*)&o;
    #pragma unroll
    for (int j = 0; j < 4; ++j) {
        __half wm = __hmin(Hm[2*j+3], __hmin(Hm[2*j+4], Hm[2*j+5]));
        __half wM = __hmax(HM[2*j+3], __hmax(HM[2*j+4], HM[2*j+5]));
        float a1 = fmaf(__half2float(wm), scale, shift);
        float a2 = fmaf(__half2float(wM), scale, shift);
        float lo = fminf(a1, a2);
        float hi = fmaxf(a1, a2);
        float r  = 0.5f*hi*(1.0f + erff(hi*0.70710678118654752f));
        if (hi < 0.f) {
            float gl = 0.5f*lo*(1.0f + erff(lo*0.70710678118654752f));
            r = fmaxf(r, gl);
        }
        ov[j] = r;
    }
    *(float4*)&out[(size_t)(t2*PH + py)*PW + px] = o;
}

// ---------------------------------------------------------------------------
extern "C" void kernel_launch(void* const* d_in, const int* in_sizes, int n_in,
                              void* d_out, int out_size) {
    const float* x      = (const float*)d_in[0];
    const float* conv_w = (const float*)d_in[1];
    const float* conv_b = (const float*)d_in[2];
    const float* gamma  = (const float*)d_in[3];
    const float* beta   = (const float*)d_in[4];
    float* out = (float*)d_out;

    cudaFuncSetAttribute(conv_mma_kernel,
                         cudaFuncAttributeMaxDynamicSharedMemorySize, CONV_SMEM);

    wprep_kernel<<<(CO*32 + 255)/256, 256>>>(conv_w);
    conv_mma_kernel<<<dim3(56, B_), CONV_THREADS, CONV_SMEM>>>(x, conv_b);
    finalize_stats_kernel<<<1, CO>>>(gamma, beta);
    bn_gelu_pool_kernel<<<POOL_GROUPS/POOL_THREADS, POOL_THREADS>>>(out);
}

// round 12
// speedup vs baseline: 1.7834x; 1.0167x over previous
#include <cuda_runtime.h>
#include <cuda_fp16.h>
#include <math.h>
#include <stdint.h>

#define B_    32
#define CIN   3
#define HIN   224
#define WIN   224
#define CO    192
#define OH    112
#define OW    112
#define PH    56
#define PW    56
#define NPC   (B_*OH*OW)   // 401408

// padded y layout: per (b,c) plane = 113 rows x 128 halves.
// row 0 = NaN halo; y row r at row r+1; y col c at col c+4.
#define PP     128
#define PROWS  113

// -------- device scratch ----------------------------------------------------
__device__ __half g_yh[(size_t)B_*CO*PROWS*PP];   // ~178 MB padded conv output
__device__ __half g_wh[CO*32];                    // fp16 weights, taps 27..31 = 0
__device__ float g_sum[CO];                       // zeroed at load; finalize re-zeroes
__device__ float g_sq[CO];
__device__ float g_scale[CO];
__device__ float g_shift[CO];

// ---------------------------------------------------------------------------
__global__ void wprep_kernel(const float* __restrict__ conv_w) {
    int i = blockIdx.x*256 + threadIdx.x;
    if (i >= CO*32) return;
    int co = i >> 5, k = i & 31;
    float v = (k < 27) ? conv_w[co*27 + k] : 0.f;
    g_wh[i] = __float2half(v);
}

// ---------------------------------------------------------------------------
__device__ __forceinline__ void mma16816(float& d0, float& d1, float& d2, float& d3,
                                         uint32_t a0, uint32_t a1, uint32_t a2, uint32_t a3,
                                         uint32_t b0, uint32_t b1) {
    asm volatile(
        "mma.sync.aligned.m16n8k16.row.col.f32.f16.f16.f32 "
        "{%0,%1,%2,%3},{%4,%5,%6,%7},{%8,%9},{%0,%1,%2,%3};"
        : "+f"(d0), "+f"(d1), "+f"(d2), "+f"(d3)
        : "r"(a0), "r"(a1), "r"(a2), "r"(a3), "r"(b0), "r"(b1));
}

__device__ __forceinline__ void ldsm_x4(uint32_t& r0, uint32_t& r1,
                                        uint32_t& r2, uint32_t& r3, uint32_t p) {
    asm volatile("ldmatrix.sync.aligned.m8n8.x4.shared.b16 {%0,%1,%2,%3},[%4];"
                 : "=r"(r0), "=r"(r1), "=r"(r2), "=r"(r3) : "r"(p));
}

__device__ __forceinline__ void bulk_copy_s2g(void* gdst, uint32_t ssrc, int bytes) {
    asm volatile("cp.async.bulk.global.shared::cta.bulk_group [%0], [%1], %2;"
                 :: "l"(gdst), "r"(ssrc), "r"(bytes) : "memory");
}

// ---------------------------------------------------------------------------
// Implicit-GEMM conv, 2 output rows per block.
// 448 thr = 14 warps. Warp w: mh=w&1 -> 96 channels, ng=w>>1 -> 16 cols.
// Epilogue rows copied out via cp.async.bulk (DMA), overlapping next B-build.
#define CONV_THREADS 448
#define RPB     2
#define XROWS   5
#define XPITCH  232
#define APITCH  40
#define BPITCH  40
#define SYP     136                          // staging pitch (halves)
#define A_OFF   0                            // 192*40  = 7680
#define X_OFF   (CO*APITCH)                  // 15*232  = 3480
#define B_OFF   (X_OFF + CIN*XROWS*XPITCH)   // 112*40  = 4480
#define Y_OFF   (B_OFF + OW*BPITCH)          // 192*136 = 26112
#define H_TOT   (Y_OFF + CO*SYP)             // 41752 halves
#define NF      (192 + 2*CO*7)               // bias + sum/sq slots = 2880 floats
#define CONV_SMEM (H_TOT*2 + NF*4)           // 83504 + 11520 = 95024 B

__global__ __launch_bounds__(CONV_THREADS, 2)
void conv_mma_kernel(const float* __restrict__ x,
                     const float* __restrict__ conv_b) {
    extern __shared__ __half sm[];
    __half* A_s = sm + A_OFF;
    __half* sX  = sm + X_OFF;
    __half* B_s = sm + B_OFF;
    __half* sY  = sm + Y_OFF;
    float*  sBias = (float*)(sm + H_TOT);
    float*  sSumP = sBias + 192;         // [192][7]
    float*  sSqP  = sSumP + CO*7;        // [192][7]

    const int tid  = threadIdx.x;
    const int lane = tid & 31;
    const int w    = tid >> 5;
    const int rt   = blockIdx.x;    // 2-row tile, 0..55
    const int b    = blockIdx.y;

    if (tid < 192) sBias[tid] = conv_b[tid];
    for (int i = tid; i < CO*7; i += CONV_THREADS) { sSumP[i] = 0.f; sSqP[i] = 0.f; }

    // ---- A: copy prebuilt fp16 weights ----
    {
        const uint32_t* src = (const uint32_t*)g_wh;
        uint32_t* dst = (uint32_t*)A_s;          // pitch 20 uints
        for (int i = tid; i < CO*16; i += CONV_THREADS) {
            int co = i >> 4, ku = i & 15;
            dst[co*20 + ku] = src[i];
        }
    }

    // ---- stage 5 rows x 3 ci, coalesced: warp -> (ci,row) pair ----
    for (int pair = w; pair < CIN*XROWS; pair += 14) {
        int ci = pair / XROWS;
        int r  = pair - ci*XROWS;
        int gr = 4*rt - 1 + r;
        __half* row = &sX[pair*XPITCH];
        if (gr < 0 || gr >= HIN) {
            if (lane < 29) *(uint4*)&row[8*lane] = make_uint4(0,0,0,0);
        } else {
            const float4* xb = (const float4*)(x + ((size_t)(b*CIN + ci)*HIN + gr)*WIN);
            float4 a = xb[lane];                       // gc 4l..4l+3
            *(__half2*)&row[2 + 4*lane]     = __floats2half2_rn(a.x, a.y);
            *(__half2*)&row[2 + 4*lane + 2] = __floats2half2_rn(a.z, a.w);
            if (lane < 24) {
                float4 c4 = xb[lane + 32];             // gc 128+4l..
                *(__half2*)&row[2 + 4*(lane+32)]     = __floats2half2_rn(c4.x, c4.y);
                *(__half2*)&row[2 + 4*(lane+32) + 2] = __floats2half2_rn(c4.z, c4.w);
            } else if (lane == 24) {
                *(__half2*)&row[0] = __floats2half2_rn(0.f, 0.f);   // cols 0..1 pad
            }
        }
    }

    // ---- staging NaN halo cols (once): cols 0..3 and 116..127 of sY ----
    {
        const __half2 NH2 = __halves2half2(__ushort_as_half((unsigned short)0x7e00),
                                           __ushort_as_half((unsigned short)0x7e00));
        for (int i = tid; i < CO*8; i += CONV_THREADS) {
            int ch = i >> 3, j = i & 7;
            int col = (j < 2) ? 2*j : 116 + 2*(j - 2);
            *(__half2*)&sY[ch*SYP + col] = NH2;
        }
    }

    // ---- top halo row 0 in gmem (rt==0 blocks only) ----
    if (rt == 0) {
        uint4 nv;
        nv.x = nv.y = nv.z = nv.w = 0x7e007e00u;
        for (int i = tid; i < CO*16; i += CONV_THREADS) {
            int ch = i >> 4, cu = i & 15;
            *(uint4*)(g_yh + ((size_t)(b*CO + ch)*PROWS)*PP + cu*8) = nv;
        }
    }
    __syncthreads();

    const int mh = w & 1;
    const int ng = w >> 1;
    const int qr = lane >> 2;
    const int qc = lane & 3;

    const uint32_t a_base = (uint32_t)__cvta_generic_to_shared(A_s)
                          + (uint32_t)((lane & 15) * (APITCH*2))
                          + (uint32_t)((lane & 16) ? 16 : 0)
                          + (uint32_t)(mh ? 6*16*APITCH*2 : 0);

    const uint32_t sy_row = (tid < 192)
        ? (uint32_t)__cvta_generic_to_shared(&sY[tid*SYP]) : 0u;

    #pragma unroll 1
    for (int oyl = 0; oyl < RPB; ++oyl) {
        // ---- build B [112 n][40 k]: lane = tap, warp covers 8 n values ----
        {
            int ci = lane / 9;
            int rr = lane - ci*9;
            int ky = rr / 3;
            int kx = rr - ky*3;
            const __half* xs = &sX[(ci*XROWS + 2*oyl + ky)*XPITCH + kx + 1];
            #pragma unroll
            for (int j = 0; j < 8; ++j) {
                int n = w + 14*j;
                __half v = __float2half(0.f);
                if (lane < 27) v = xs[2*n];
                B_s[n*BPITCH + lane] = v;
            }
        }
        // previous bulk copies must finish reading sY before we overwrite it
        if (tid < 192)
            asm volatile("cp.async.bulk.wait_group 0;" ::: "memory");
        __syncthreads();

        // ---- MMA ----
        float acc[6][2][4];
        #pragma unroll
        for (int mi = 0; mi < 6; ++mi)
            #pragma unroll
            for (int ni = 0; ni < 2; ++ni)
                #pragma unroll
                for (int j = 0; j < 4; ++j) acc[mi][ni][j] = 0.f;

        #pragma unroll
        for (int ks = 0; ks < 2; ++ks) {
            const int kb = ks*16 + 2*qc;
            uint32_t bf[2][2];
            #pragma unroll
            for (int ni = 0; ni < 2; ++ni) {
                const __half* bp = &B_s[(ng*16 + ni*8 + qr)*BPITCH + kb];
                bf[ni][0] = *(const uint32_t*)(bp);
                bf[ni][1] = *(const uint32_t*)(bp + 8);
            }
            #pragma unroll
            for (int mi = 0; mi < 6; ++mi) {
                uint32_t a0, a1, a2, a3;
                ldsm_x4(a0, a1, a2, a3,
                        a_base + (uint32_t)(mi*16*APITCH*2 + ks*32));
                #pragma unroll
                for (int ni = 0; ni < 2; ++ni)
                    mma16816(acc[mi][ni][0], acc[mi][ni][1], acc[mi][ni][2], acc[mi][ni][3],
                             a0, a1, a2, a3, bf[ni][0], bf[ni][1]);
            }
        }

        // ---- bias, stats (smem slots), staging STS ----
        #pragma unroll
        for (int mi = 0; mi < 6; ++mi) {
            const int R0 = (mh*6 + mi)*16 + qr;
            const int R8 = R0 + 8;
            const float bias0 = sBias[R0];
            const float bias8 = sBias[R8];
            float s0 = 0.f, q0 = 0.f, s8 = 0.f, q8 = 0.f;
            #pragma unroll
            for (int ni = 0; ni < 2; ++ni) {
                const int C = ng*16 + ni*8 + 2*qc;
                float v0 = acc[mi][ni][0] + bias0;
                float v1 = acc[mi][ni][1] + bias0;
                float v2 = acc[mi][ni][2] + bias8;
                float v3 = acc[mi][ni][3] + bias8;
                *(__half2*)&sY[R0*SYP + 4 + C] = __floats2half2_rn(v0, v1);
                *(__half2*)&sY[R8*SYP + 4 + C] = __floats2half2_rn(v2, v3);
                s0 += v0 + v1;  q0 += v0*v0 + v1*v1;
                s8 += v2 + v3;  q8 += v2*v2 + v3*v3;
            }
            #pragma unroll
            for (int o = 1; o <= 2; o <<= 1) {
                s0 += __shfl_xor_sync(0xffffffffu, s0, o);
                q0 += __shfl_xor_sync(0xffffffffu, q0, o);
                s8 += __shfl_xor_sync(0xffffffffu, s8, o);
                q8 += __shfl_xor_sync(0xffffffffu, q8, o);
            }
            if (qc == 0) {
                sSumP[R0*7 + ng] += s0;
                sSqP [R0*7 + ng] += q0;
                sSumP[R8*7 + ng] += s8;
                sSqP [R8*7 + ng] += q8;
            }
        }
        __syncthreads();

        // ---- DMA copy-out: one 256B bulk copy per channel row ----
        if (tid < 192) {
            const int OY = 2*rt + oyl;
            asm volatile("fence.proxy.async.shared::cta;" ::: "memory");
            bulk_copy_s2g(g_yh + ((size_t)(b*CO + tid)*PROWS + OY + 1)*PP,
                          sy_row, 256);
            asm volatile("cp.async.bulk.commit_group;" ::: "memory");
        }
    }

    // ---- block-level stats reduce, then drain bulk copies ----
    if (tid < 192) {
        float s = 0.f, q = 0.f;
        #pragma unroll
        for (int j = 0; j < 7; ++j) { s += sSumP[tid*7 + j]; q += sSqP[tid*7 + j]; }
        atomicAdd(&g_sum[tid], s);
        atomicAdd(&g_sq [tid], q);
        asm volatile("cp.async.bulk.wait_group 0;" ::: "memory");
    }
}

// ---------------------------------------------------------------------------
__global__ void finalize_stats_kernel(const float* __restrict__ gamma,
                                      const float* __restrict__ beta) {
    int c = threadIdx.x;
    if (c >= CO) return;
    float invN  = 1.0f / (float)NPC;
    float mean  = g_sum[c] * invN;
    float var   = g_sq[c] * invN - mean*mean;
    float inv   = rsqrtf(var + 1e-5f);
    float scale = gamma[c] * inv;
    g_scale[c]  = scale;
    g_shift[c]  = beta[c] - mean*scale;
    g_sum[c] = 0.f;   // re-zero for next graph replay
    g_sq [c] = 0.f;
}

// ---------------------------------------------------------------------------
// BN + GELU + MaxPool, direct from padded gmem, 2 pool rows per thread
// (rows py0,py0+1 share conv row 2py0+2 -> 5 rows read instead of 6).
#define POOL_THREADS 256
#define POOL_TOTAL  (B_*CO*(PH/2)*(PW/4))   // 2,408,448 -> 9408 blocks

__global__ __launch_bounds__(POOL_THREADS)
void bn_gelu_pool_kernel(float* __restrict__ out) {
    const int idx = blockIdx.x*POOL_THREADS + threadIdx.x;
    const int g   = idx % 14;            // col group: px = 4g
    const int t1  = idx / 14;
    const int u   = t1 % 28;             // row pair: py0 = 2u
    const int t2  = t1 / 28;             // b*CO + ch
    const int ch  = t2 % CO;
    const int px  = 4*g;
    const int py0 = 2*u;

    const float scale = g_scale[ch];
    const float shift = g_shift[ch];

    const __half* base = g_yh + (size_t)t2*(PROWS*PP) + (size_t)(4*u)*PP + 2*px;

    union U { uint4 v[2]; __half2 h[8]; };
    U r0, r1, r2;
    r0.v[0] = *(const uint4*)(base);         r0.v[1] = *(const uint4*)(base + 8);
    r1.v[0] = *(const uint4*)(base + PP);    r1.v[1] = *(const uint4*)(base + PP + 8);
    r2.v[0] = *(const uint4*)(base + 2*PP);  r2.v[1] = *(const uint4*)(base + 2*PP + 8);

    __half2 vmin[8], vmax[8];
    #pragma unroll
    for (int j = 0; j < 8; ++j) {
        vmax[j] = __hmax2(__hmax2(r0.h[j], r1.h[j]), r2.h[j]);
        vmin[j] = __hmin2(__hmin2(r0.h[j], r1.h[j]), r2.h[j]);
    }

    float* op0 = &out[(size_t)(t2*PH + py0)*PW + px];

    {   // outputs for py0
        const __half* Hm = (const __half*)vmin;
        const __half* HM = (const __half*)vmax;
        float4 o; float* ov = (float*)&o;
        #pragma unroll
        for (int j = 0; j < 4; ++j) {
            __half wm = __hmin(Hm[2*j+3], __hmin(Hm[2*j+4], Hm[2*j+5]));
            __half wM = __hmax(HM[2*j+3], __hmax(HM[2*j+4], HM[2*j+5]));
            float a1 = fmaf(__half2float(wm), scale, shift);
            float a2 = fmaf(__half2float(wM), scale, shift);
            float lo = fminf(a1, a2);
            float hi = fmaxf(a1, a2);
            float r  = 0.5f*hi*(1.0f + erff(hi*0.70710678118654752f));
            if (hi < 0.f) {
                float gl = 0.5f*lo*(1.0f + erff(lo*0.70710678118654752f));
                r = fmaxf(r, gl);
            }
            ov[j] = r;
        }
        *(float4*)op0 = o;
    }

    // rows 3,4 (reuse r2): window rows 2..4 for py0+1
    U r3, r4;
    r3.v[0] = *(const uint4*)(base + 3*PP);  r3.v[1] = *(const uint4*)(base + 3*PP + 8);
    r4.v[0] = *(const uint4*)(base + 4*PP);  r4.v[1] = *(const uint4*)(base + 4*PP + 8);

    #pragma unroll
    for (int j = 0; j < 8; ++j) {
        vmax[j] = __hmax2(__hmax2(r2.h[j], r3.h[j]), r4.h[j]);
        vmin[j] = __hmin2(__hmin2(r2.h[j], r3.h[j]), r4.h[j]);
    }

    {   // outputs for py0+1
        const __half* Hm = (const __half*)vmin;
        const __half* HM = (const __half*)vmax;
        float4 o; float* ov = (float*)&o;
        #pragma unroll
        for (int j = 0; j < 4; ++j) {
            __half wm = __hmin(Hm[2*j+3], __hmin(Hm[2*j+4], Hm[2*j+5]));
            __half wM = __hmax(HM[2*j+3], __hmax(HM[2*j+4], HM[2*j+5]));
            float a1 = fmaf(__half2float(wm), scale, shift);
            float a2 = fmaf(__half2float(wM), scale, shift);
            float lo = fminf(a1, a2);
            float hi = fmaxf(a1, a2);
            float r  = 0.5f*hi*(1.0f + erff(hi*0.70710678118654752f));
            if (hi < 0.f) {
                float gl = 0.5f*lo*(1.0f + erff(lo*0.70710678118654752f));
                r = fmaxf(r, gl);
            }
            ov[j] = r;
        }
        *(float4*)(op0 + PW) = o;
    }
}

// ---------------------------------------------------------------------------
extern "C" void kernel_launch(void* const* d_in, const int* in_sizes, int n_in,
                              void* d_out, int out_size) {
    const float* x      = (const float*)d_in[0];
    const float* conv_w = (const float*)d_in[1];
    const float* conv_b = (const float*)d_in[2];
    const float* gamma  = (const float*)d_in[3];
    const float* beta   = (const float*)d_in[4];
    float* out = (float*)d_out;

    cudaFuncSetAttribute(conv_mma_kernel,
                         cudaFuncAttributeMaxDynamicSharedMemorySize, CONV_SMEM);

    wprep_kernel<<<(CO*32 + 255)/256, 256>>>(conv_w);
    conv_mma_kernel<<<dim3(56, B_), CONV_THREADS, CONV_SMEM>>>(x, conv_b);
    finalize_stats_kernel<<<1, CO>>>(gamma, beta);
    bn_gelu_pool_kernel<<<POOL_TOTAL/POOL_THREADS, POOL_THREADS>>>(out);
}